// round 16
// baseline (speedup 1.0000x reference)
#include <cuda_runtime.h>
#include <cuda_fp16.h>
#include <cstdint>
#include <cstring>

#define NB    4
#define QLEN  4096
#define HIDD  1024
#define NHEAD 16
#define HDIM  64
#define TXTN  77
#define IPTN  8
#define CDIM  768
#define ENCR  85   // TXT + IPT

// ---------------- scratch (no allocation allowed) ----------------
__device__ float  g_Wq  [HIDD*HIDD];   // fp32-exact (gate path)
__device__ __half g_WqT [HIDD*HIDD];   // fp16, TRANSPOSED [N,K]
__device__ __half g_WoT [HIDD*HIDD];   // fp16, TRANSPOSED [N,K]
__device__ float  g_WkR [CDIM*HIDD];
__device__ float  g_WvR [CDIM*HIDD];
__device__ __half g_hsH [NB*QLEN*HIDD];  // hs converted to half
__device__ __half g_qH  [NB*QLEN*HIDD];  // Q projection, half
__device__ __half g_hidH[NB*QLEN*HIDD];  // attention output, half
__device__ float  g_kk  [NB*TXTN*HIDD];
__device__ float  g_vv  [NB*TXTN*HIDD];
__device__ float  g_ipk [NB*IPTN*HIDD];
__device__ float  g_ipv [NB*IPTN*HIDD];
__device__ float  g_ehs [NB*TXTN*CDIM];   // pre-rounded to tf32
__device__ float  g_ip  [NB*IPTN*CDIM];   // exact (gate path reads it)
__device__ float  g_ipsum[NB*CDIM];
__device__ float  g_ipkS[NB*HIDD];
__device__ float  g_wqs [NB*HIDD];
__device__ float  g_w   [NB*QLEN];
__device__ float  g_mm  [2*NB];

typedef unsigned long long u64;

__device__ __forceinline__ uint32_t h2u(__half2 h) {
    uint32_t u;
    memcpy(&u, &h, 4);
    return u;
}
__device__ __forceinline__ __half2 u2h(uint32_t u) {
    __half2 h;
    memcpy(&h, &u, 4);
    return h;
}

__device__ __forceinline__ uint32_t f2tf(float x) {
    uint32_t r;
    asm("cvt.rna.tf32.f32 %0, %1;" : "=r"(r) : "f"(x));
    return r;
}
__device__ __forceinline__ float roundtf(float x) {
    return __uint_as_float(f2tf(x));
}

__device__ __forceinline__ void cp16g(uint32_t s, const void* g) {
    asm volatile("cp.async.ca.shared.global [%0], [%1], 16;" :: "r"(s), "l"(g));
}
__device__ __forceinline__ void cp_commit() {
    asm volatile("cp.async.commit_group;");
}
template<int N_> __device__ __forceinline__ void cp_wait() {
    asm volatile("cp.async.wait_group %0;" :: "n"(N_));
}

__device__ __forceinline__ void mma_fp16(float* c, const uint32_t* a, const uint32_t* b) {
    asm volatile("mma.sync.aligned.m16n8k16.row.col.f32.f16.f16.f32 "
        "{%0,%1,%2,%3}, {%4,%5,%6,%7}, {%8,%9}, {%0,%1,%2,%3};"
        : "+f"(c[0]), "+f"(c[1]), "+f"(c[2]), "+f"(c[3])
        : "r"(a[0]), "r"(a[1]), "r"(a[2]), "r"(a[3]), "r"(b[0]), "r"(b[1]));
}

// ================= FP16 tensor-core GEMM: C[M,N] = A[M,K] @ Bt[N,K]^T ========
#define HPAD 72
#define GH_STAGE (128*HPAD*2)
#define GH_SMEM  (4*GH_STAGE)

template<bool HOUT>
__global__ __launch_bounds__(256) void gemm_fp16(
    const __half* __restrict__ A, const __half* __restrict__ Bt,
    void* __restrict__ Cv, const float* __restrict__ bias, int K, int N)
{
    extern __shared__ __align__(16) char sm[];
    const uint32_t sA = (uint32_t)__cvta_generic_to_shared(sm);
    const uint32_t sB = sA + 2*GH_STAGE;

    const int tid  = threadIdx.x;
    const int lane = tid & 31;
    const int warp = tid >> 5;
    const int wm = (warp >> 1) * 32;
    const int wn = (warp & 1) * 64;
    const int row0 = blockIdx.y * 128;
    const int n0   = blockIdx.x * 128;

    const __half* Ab = A  + (size_t)row0 * K;
    const __half* Bb = Bt + (size_t)n0 * K;

    float acc[2][8][4];
#pragma unroll
    for (int i = 0; i < 2; i++)
#pragma unroll
        for (int j = 0; j < 8; j++)
#pragma unroll
            for (int r = 0; r < 4; r++) acc[i][j][r] = 0.f;

    auto load_stage = [&](int s, int buf) {
        const uint32_t ab = sA + (uint32_t)buf * GH_STAGE;
        const uint32_t bb = sB + (uint32_t)buf * GH_STAGE;
        const int k0 = s * 64;
#pragma unroll
        for (int i = 0; i < 4; i++) {
            int c = tid + 256 * i;
            int r = c >> 3, cc = c & 7;
            cp16g(ab + (uint32_t)(r * (HPAD*2) + cc * 16),
                  Ab + (size_t)r * K + k0 + cc * 8);
            cp16g(bb + (uint32_t)(r * (HPAD*2) + cc * 16),
                  Bb + (size_t)r * K + k0 + cc * 8);
        }
    };

    const int nstage = K / 64;
    load_stage(0, 0);
    cp_commit();

    for (int s = 0; s < nstage; s++) {
        const int buf = s & 1;
        if (s + 1 < nstage) {
            load_stage(s + 1, buf ^ 1);
            cp_commit();
            cp_wait<1>();
        } else {
            cp_wait<0>();
        }
        __syncthreads();

        const uint32_t ab = sA + (uint32_t)buf * GH_STAGE;
        const uint32_t bb = sB + (uint32_t)buf * GH_STAGE;
        const int g = lane >> 2, t = lane & 3;

#pragma unroll
        for (int ks = 0; ks < 64; ks += 16) {
            uint32_t af[2][4];
#pragma unroll
            for (int im = 0; im < 2; im++) {
                uint32_t base = ab + (uint32_t)((wm + im*16 + g) * (HPAD*2) + (ks + 2*t) * 2);
                asm volatile("ld.shared.b32 %0, [%1];" : "=r"(af[im][0]) : "r"(base));
                asm volatile("ld.shared.b32 %0, [%1];" : "=r"(af[im][1]) : "r"(base + 8*(HPAD*2)));
                asm volatile("ld.shared.b32 %0, [%1];" : "=r"(af[im][2]) : "r"(base + 16));
                asm volatile("ld.shared.b32 %0, [%1];" : "=r"(af[im][3]) : "r"(base + 8*(HPAD*2) + 16));
            }
            uint32_t bf[8][2];
#pragma unroll
            for (int jn = 0; jn < 8; jn++) {
                uint32_t base = bb + (uint32_t)((wn + jn*8 + g) * (HPAD*2) + (ks + 2*t) * 2);
                asm volatile("ld.shared.b32 %0, [%1];" : "=r"(bf[jn][0]) : "r"(base));
                asm volatile("ld.shared.b32 %0, [%1];" : "=r"(bf[jn][1]) : "r"(base + 16));
            }
#pragma unroll
            for (int im = 0; im < 2; im++)
#pragma unroll
                for (int jn = 0; jn < 8; jn++)
                    mma_fp16(acc[im][jn], af[im], bf[jn]);
        }
        __syncthreads();
    }

#pragma unroll
    for (int im = 0; im < 2; im++) {
#pragma unroll
        for (int jn = 0; jn < 8; jn++) {
            int r = row0 + wm + im*16 + (lane >> 2);
            int c = n0 + wn + jn*8 + 2*(lane & 3);
            float2 v0 = make_float2(acc[im][jn][0], acc[im][jn][1]);
            float2 v1 = make_float2(acc[im][jn][2], acc[im][jn][3]);
            if (HOUT) {
                __half* C = (__half*)Cv;
                *(uint32_t*)(C + (size_t)r*N + c)       = h2u(__floats2half2_rn(v0.x, v0.y));
                *(uint32_t*)(C + (size_t)(r + 8)*N + c) = h2u(__floats2half2_rn(v1.x, v1.y));
            } else {
                float* C = (float*)Cv;
                if (bias) {
                    float2 bv = *(const float2*)(bias + c);
                    v0.x += bv.x; v0.y += bv.y;
                    v1.x += bv.x; v1.y += bv.y;
                }
                *(float2*)(C + (size_t)r*N + c)       = v0;
                *(float2*)(C + (size_t)(r + 8)*N + c) = v1;
            }
        }
    }
}

// ---------------- hs -> half (one-time convert) ----------------
__global__ void hs2h_kernel(const float* __restrict__ hs, __half* __restrict__ out)
{
    int i = (blockIdx.x * 256 + threadIdx.x) * 4;
    float4 v = *(const float4*)(hs + i);
    __half2 h0 = __floats2half2_rn(v.x, v.y);
    __half2 h1 = __floats2half2_rn(v.z, v.w);
    uint2 w = make_uint2(h2u(h0), h2u(h1));
    *(uint2*)(out + i) = w;
}

// ---------------- fuse + transpose (Wq / Wo): out half [N,K] ----------------
__global__ __launch_bounds__(256) void fuse_t_kernel(
    const float* __restrict__ W, const float* __restrict__ dn,
    const float* __restrict__ up, __half* __restrict__ outT,
    float* __restrict__ outF)
{
    __shared__ float t[32][33];
    const int bx = blockIdx.x, by = blockIdx.y;
    const int tx = threadIdx.x & 31, ty = threadIdx.x >> 5;
#pragma unroll
    for (int i = 0; i < 4; i++) {
        int rr = by * 32 + ty + 8 * i;
        int cc = bx * 32 + tx;
        float acc = W[rr * HIDD + cc];
#pragma unroll
        for (int j = 0; j < 4; j++)
            acc = fmaf(dn[rr * 4 + j], up[j * HIDD + cc], acc);
        if (outF) outF[rr * HIDD + cc] = acc;
        t[ty + 8 * i][tx] = acc;
    }
    __syncthreads();
#pragma unroll
    for (int i = 0; i < 4; i++) {
        int rr = by * 32 + tx;
        int cc = bx * 32 + ty + 8 * i;
        outT[(size_t)cc * HIDD + rr] = __float2half_rn(t[tx][ty + 8 * i]);
    }
}

// ---------------- fold LoRA into Wk/Wv (untransposed, tf32-rounded) ----------
__global__ void fuse_kv_kernel(
    const float* __restrict__ Wk, const float* __restrict__ kd, const float* __restrict__ ku,
    const float* __restrict__ Wv, const float* __restrict__ vd, const float* __restrict__ vu,
    float* __restrict__ oWkR, float* __restrict__ oWvR)
{
    const int NK = CDIM*HIDD;
    int idx = blockIdx.x * 256 + threadIdx.x;
    const float *W, *dn, *up;
    float* oR;
    int li;
    if (idx < NK)        { W=Wk; dn=kd; up=ku; oR=oWkR; li=idx; }
    else if (idx < 2*NK) { W=Wv; dn=vd; up=vu; oR=oWvR; li=idx-NK; }
    else return;
    int r = li >> 10, c = li & 1023;
    float acc = W[li];
#pragma unroll
    for (int j = 0; j < 4; j++)
        acc = fmaf(dn[r*4 + j], up[j*HIDD + c], acc);
    oR[li] = roundtf(acc);
}

// ---------------- pack encoder slices contiguous ----------------
__global__ void pack_enc_kernel(const float* __restrict__ enc,
                                float* __restrict__ ehs,
                                float* __restrict__ ipb)
{
    int idx = blockIdx.x * 256 + threadIdx.x;
    const int n1 = NB*TXTN*CDIM;
    const int n2 = NB*IPTN*CDIM;
    if (idx < n1) {
        int b = idx / (TXTN*CDIM);
        int rem = idx - b*(TXTN*CDIM);
        int t = rem / CDIM, c = rem - t*CDIM;
        ehs[idx] = roundtf(enc[((size_t)b*ENCR + t)*CDIM + c]);
    } else if (idx < n1 + n2) {
        int k = idx - n1;
        int b = k / (IPTN*CDIM);
        int rem = k - b*(IPTN*CDIM);
        int t = rem / CDIM, c = rem - t*CDIM;
        ipb[k] = enc[((size_t)b*ENCR + TXTN + t)*CDIM + c];
    }
}

// ================= mma.sync TF32 GEMM body (small enc/ip projections) =======
#define APAD 20
#define BPAD 136

__device__ __forceinline__ void mma_tf32(float* c, const uint32_t* a, const uint32_t* b) {
    asm volatile("mma.sync.aligned.m16n8k8.row.col.f32.tf32.tf32.f32 "
        "{%0,%1,%2,%3}, {%4,%5,%6,%7}, {%8,%9}, {%0,%1,%2,%3};"
        : "+f"(c[0]), "+f"(c[1]), "+f"(c[2]), "+f"(c[3])
        : "r"(a[0]), "r"(a[1]), "r"(a[2]), "r"(a[3]), "r"(b[0]), "r"(b[1]));
}
__device__ __forceinline__ uint32_t ldfragc(const float* p) {
    return f2tf(*p);
}

__device__ __forceinline__ void gemm_body_tf32(
    const float* __restrict__ A, const float* __restrict__ B,
    float* __restrict__ C, int M, int N, int K, int bx, int by)
{
    __shared__ float As[2][128*APAD];
    __shared__ float Bs[2][16*BPAD];

    const int tid  = threadIdx.x;
    const int lane = tid & 31;
    const int warp = tid >> 5;
    const int wm = (warp >> 1) * 64;
    const int wn = (warp & 1) * 64;

    const float* Bg = B + bx * 128;

    const int a_colv = tid & 3;
    const int a_rowb = tid >> 2;
    const int b_colv = tid & 31;
    const int b_rowb = tid >> 5;

    const uint32_t as0 = (uint32_t)__cvta_generic_to_shared(&As[0][0]);
    const uint32_t bs0 = (uint32_t)__cvta_generic_to_shared(&Bs[0][0]);

    float acc[4][8][4];
#pragma unroll
    for (int i = 0; i < 4; i++)
#pragma unroll
        for (int j = 0; j < 8; j++)
#pragma unroll
            for (int r = 0; r < 4; r++) acc[i][j][r] = 0.f;

    auto load_stage = [&](int k0, int buf) {
        uint32_t asb = as0 + (uint32_t)buf * (128*APAD*4);
        uint32_t bsb = bs0 + (uint32_t)buf * (16*BPAD*4);
#pragma unroll
        for (int i = 0; i < 4; i++) {
            int row = a_rowb + i*32;
            int rg = by*128 + row; if (rg > M-1) rg = M-1;
            cp16g(asb + (uint32_t)(row*APAD + a_colv*4)*4,
                 A + (size_t)rg*K + k0 + a_colv*4);
        }
#pragma unroll
        for (int i = 0; i < 4; i++) {
            int row = b_rowb + i*4;
            cp16g(bsb + (uint32_t)(row*BPAD + b_colv*4)*4,
                 Bg + (size_t)(k0 + row)*N + b_colv*4);
        }
    };

    const int nstage = K / 16;
    load_stage(0, 0);
    cp_commit();

    int buf = 0;
    for (int s = 0; s < nstage; s++) {
        if (s + 1 < nstage) {
            load_stage((s + 1)*16, buf ^ 1);
            cp_commit();
            cp_wait<1>();
        } else {
            cp_wait<0>();
        }
        __syncthreads();

        const float* as = As[buf];
        const float* bs = Bs[buf];
#pragma unroll
        for (int ks = 0; ks < 16; ks += 8) {
            uint32_t af[4][4];
#pragma unroll
            for (int im = 0; im < 4; im++) {
                const float* ap = as + (wm + im*16 + (lane >> 2))*APAD + ks + (lane & 3);
                af[im][0] = ldfragc(ap);
                af[im][1] = ldfragc(ap + 8*APAD);
                af[im][2] = ldfragc(ap + 4);
                af[im][3] = ldfragc(ap + 8*APAD + 4);
            }
            uint32_t bf[8][2];
#pragma unroll
            for (int jn = 0; jn < 8; jn++) {
                const float* bp = bs + (ks + (lane & 3))*BPAD + wn + jn*8 + (lane >> 2);
                bf[jn][0] = ldfragc(bp);
                bf[jn][1] = ldfragc(bp + 4*BPAD);
            }
#pragma unroll
            for (int im = 0; im < 4; im++)
#pragma unroll
                for (int jn = 0; jn < 8; jn++)
                    mma_tf32(acc[im][jn], af[im], bf[jn]);
        }
        __syncthreads();
        buf ^= 1;
    }

#pragma unroll
    for (int im = 0; im < 4; im++) {
#pragma unroll
        for (int jn = 0; jn < 8; jn++) {
            int r = by*128 + wm + im*16 + (lane >> 2);
            int c = bx*128 + wn + jn*8 + 2*(lane & 3);
            float2 v0 = make_float2(acc[im][jn][0], acc[im][jn][1]);
            float2 v1 = make_float2(acc[im][jn][2], acc[im][jn][3]);
            if (r < M)     *(float2*)(C + (size_t)r*N + c)       = v0;
            if (r + 8 < M) *(float2*)(C + (size_t)(r + 8)*N + c) = v1;
        }
    }
}

__global__ __launch_bounds__(128, 2) void gemm_encip(
    const float* __restrict__ ehs, const float* __restrict__ ipb,
    const float* __restrict__ WkR, const float* __restrict__ WvR,
    const float* __restrict__ Wk_ip, const float* __restrict__ Wv_ip,
    float* __restrict__ kk, float* __restrict__ vv,
    float* __restrict__ ipk, float* __restrict__ ipv)
{
    const int y = blockIdx.y, z = blockIdx.z;
    const float *A, *B; float* C; int M, by;
    if (y < 3) { A = ehs; M = NB*TXTN; by = y; B = z ? WvR  : WkR;   C = z ? vv  : kk;  }
    else       { A = ipb; M = NB*IPTN; by = 0; B = z ? Wv_ip : Wk_ip; C = z ? ipv : ipk; }
    gemm_body_tf32(A, B, C, M, HIDD, CDIM, blockIdx.x, by);
}

// ---------------- exact fp32 gate path ----------------
__global__ void ipsum_kernel(const float* __restrict__ ip, float* __restrict__ out)
{
    int idx = blockIdx.x * 256 + threadIdx.x;
    if (idx >= NB * CDIM) return;
    int b = idx / CDIM, c = idx - b*CDIM;
    float s = 0.f;
#pragma unroll
    for (int t = 0; t < IPTN; t++)
        s += ip[((size_t)b*IPTN + t)*CDIM + c];
    out[idx] = s;
}

__global__ __launch_bounds__(256) void colvec_kernel(
    const float* __restrict__ s, const float* __restrict__ W,
    float* __restrict__ out)
{
    __shared__ float ss[CDIM];
    const int b = blockIdx.y;
    const int j = blockIdx.x * 256 + threadIdx.x;
    for (int i = threadIdx.x; i < CDIM; i += 256) ss[i] = s[b*CDIM + i];
    __syncthreads();
    float acc = 0.f;
#pragma unroll 8
    for (int i = 0; i < CDIM; i++)
        acc = fmaf(ss[i], W[(size_t)i*HIDD + j], acc);
    out[b*HIDD + j] = acc;
}

__global__ __launch_bounds__(256) void wqs_matvec_kernel(
    const float* __restrict__ W, const float* __restrict__ s,
    float* __restrict__ v)
{
    __shared__ float sv[HIDD];
    const int b = blockIdx.y;
    for (int i = threadIdx.x; i < HIDD; i += 256) sv[i] = s[b*HIDD + i];
    __syncthreads();
    const int warp = threadIdx.x >> 5, lane = threadIdx.x & 31;
    const int row = blockIdx.x * 8 + warp;
    const float* wr = W + (size_t)row * HIDD;
    float acc = 0.f;
#pragma unroll
    for (int i = 0; i < 32; i++)
        acc = fmaf(wr[lane + 32*i], sv[lane + 32*i], acc);
#pragma unroll
    for (int off = 16; off > 0; off >>= 1)
        acc += __shfl_xor_sync(0xffffffffu, acc, off);
    if (lane == 0) v[b*HIDD + row] = acc;
}

__global__ __launch_bounds__(256) void wsum_kernel(const float* __restrict__ hs,
                                                   const float* __restrict__ vb,
                                                   float* __restrict__ w)
{
    __shared__ float sk[HIDD];
    const int row0 = blockIdx.x * 8;
    const int b = row0 / QLEN;
    for (int i = threadIdx.x; i < HIDD; i += 256) sk[i] = vb[b*HIDD + i];
    __syncthreads();
    const int warp = threadIdx.x >> 5, lane = threadIdx.x & 31;
    const int row = row0 + warp;
    const float* qr = hs + (size_t)row * HIDD;
    float s = 0.f;
#pragma unroll
    for (int i = 0; i < 32; i++)
        s = fmaf(qr[lane + 32*i], sk[lane + 32*i], s);
#pragma unroll
    for (int off = 16; off > 0; off >>= 1)
        s += __shfl_xor_sync(0xffffffffu, s, off);
    if (lane == 0) w[row] = 0.125f * s;
}

__global__ void minmax_kernel(const float* __restrict__ w, float* __restrict__ mm)
{
    __shared__ float smn[256], smx[256];
    const int b = blockIdx.x, tid = threadIdx.x;
    float mn = 1e30f, mx = -1e30f;
    for (int i = tid; i < QLEN; i += 256) {
        float v = w[b*QLEN + i];
        mn = fminf(mn, v); mx = fmaxf(mx, v);
    }
    smn[tid] = mn; smx[tid] = mx;
    __syncthreads();
    for (int s = 128; s > 0; s >>= 1) {
        if (tid < s) {
            smn[tid] = fminf(smn[tid], smn[tid + s]);
            smx[tid] = fmaxf(smx[tid], smx[tid + s]);
        }
        __syncthreads();
    }
    if (tid == 0) { mm[2*b] = smn[0]; mm[2*b + 1] = smx[0]; }
}

// ============ tensor-core fused attention =====================================
// CTA = (b, h, 128 q rows), 128 threads / 4 warps; warp owns 32 rows.
// S = q K'^T via m16n8k16 (K' = [kk;ipk;0] 88x64 half), per-row scalar softmax
// (thread = row), P half written in place over S, PV via m16n8k16 with V'
// stored transposed [dim][token].
#define AT_QS 72        // sQ row stride (halves)
#define AT_KS 72        // sK row stride (halves)
#define AT_VS 104       // sVt row stride (halves)
#define AT_SS 92        // sS row stride (floats)
#define AT_OFF_K  (128*AT_QS*2)              // 18432
#define AT_OFF_V  (AT_OFF_K + 88*AT_KS*2)    // 31104
#define AT_OFF_S  (AT_OFF_V + 64*AT_VS*2)    // 44416
#define AT_SMEM   (AT_OFF_S + 128*AT_SS*4)   // 91520

__global__ __launch_bounds__(128) void attn_kernel(
    const __half* __restrict__ qb,
    const float* __restrict__ kk,
    const float* __restrict__ vv,
    const float* __restrict__ ipk,
    const float* __restrict__ ipv,
    const float* __restrict__ wbuf,
    const float* __restrict__ mm,
    __half* __restrict__ hid)
{
    extern __shared__ __align__(16) char smbuf[];
    __half* sQ  = (__half*)smbuf;
    __half* sK  = (__half*)(smbuf + AT_OFF_K);
    __half* sVt = (__half*)(smbuf + AT_OFF_V);
    float*  sS  = (float*)(smbuf + AT_OFF_S);

    const int tid = threadIdx.x, lane = tid & 31, warp = tid >> 5;
    const int b = blockIdx.z, h = blockIdx.y, q0 = blockIdx.x * 128;
    const int g = lane >> 2, t = lane & 3;

    // ---- load q (scaled by 0.125, exact in half) ----
    const __half2 sc = __float2half2_rn(0.125f);
    for (int c = tid; c < 1024; c += 128) {
        int r = c >> 3, cc = c & 7;
        uint4 v = *(const uint4*)(qb + ((size_t)b*QLEN + q0 + r)*HIDD + h*HDIM + cc*8);
        uint4 w = make_uint4(h2u(__hmul2(u2h(v.x), sc)), h2u(__hmul2(u2h(v.y), sc)),
                             h2u(__hmul2(u2h(v.z), sc)), h2u(__hmul2(u2h(v.w), sc)));
        *(uint4*)(sQ + r*AT_QS + cc*8) = w;
    }
    // ---- K' = [kk(77); ipk(8); 0(3)] rows x 64, half ----
    const size_t kvbase = ((size_t)b*TXTN)*HIDD + h*HDIM;
    const size_t ipbase = ((size_t)b*IPTN)*HIDD + h*HDIM;
    for (int i = tid; i < 88*64; i += 128) {
        int tok = i >> 6, d = i & 63;
        float v = (tok < TXTN) ? kk[kvbase + (size_t)tok*HIDD + d]
                : (tok < 85)   ? ipk[ipbase + (size_t)(tok-TXTN)*HIDD + d] : 0.f;
        sK[tok*AT_KS + d] = __float2half_rn(v);
    }
    // ---- V' transposed: sVt[dim][token], tokens 0..95 (85..95 zero) ----
    for (int i = tid; i < 96*64; i += 128) {
        int tok = i / 64, d = i - tok*64;
        float v = (tok < TXTN) ? vv[kvbase + (size_t)tok*HIDD + d]
                : (tok < 85)   ? ipv[ipbase + (size_t)(tok-TXTN)*HIDD + d] : 0.f;
        sVt[d*AT_VS + tok] = __float2half_rn(v);
    }
    __syncthreads();

    const int rows0 = warp * 32;

    // ---- S-phase: S[32, 88] = q_warp @ K'^T ----
    {
        uint32_t A[2][4][4];
#pragma unroll
        for (int im = 0; im < 2; im++)
#pragma unroll
            for (int kb = 0; kb < 4; kb++) {
                const __half* base = sQ + (rows0 + 16*im + g)*AT_QS + 16*kb + 2*t;
                A[im][kb][0] = *(const uint32_t*)(base);
                A[im][kb][1] = *(const uint32_t*)(base + 8*AT_QS);
                A[im][kb][2] = *(const uint32_t*)(base + 8);
                A[im][kb][3] = *(const uint32_t*)(base + 8*AT_QS + 8);
            }
#pragma unroll
        for (int jn = 0; jn < 11; jn++) {
            uint32_t B[4][2];
#pragma unroll
            for (int kb = 0; kb < 4; kb++) {
                const __half* kp = sK + (8*jn + g)*AT_KS + 16*kb + 2*t;
                B[kb][0] = *(const uint32_t*)(kp);
                B[kb][1] = *(const uint32_t*)(kp + 8);
            }
#pragma unroll
            for (int im = 0; im < 2; im++) {
                float c[4] = {0.f, 0.f, 0.f, 0.f};
#pragma unroll
                for (int kb = 0; kb < 4; kb++)
                    mma_fp16(c, A[im][kb], B[kb]);
                float* srow = sS + (size_t)(rows0 + 16*im + g)*AT_SS + 8*jn + 2*t;
                *(float2*)(srow)            = make_float2(c[0], c[1]);
                *(float2*)(srow + 8*AT_SS)  = make_float2(c[2], c[3]);
            }
        }
    }
    __syncwarp();

    // ---- softmax phase: thread tid owns row tid ----
    {
        const int qi = q0 + tid;
        float* srow = sS + (size_t)tid * AT_SS;
        float mx = -1e30f;
        for (int j = 0; j < TXTN; j++) mx = fmaxf(mx, srow[j]);
        float sip[IPTN];
#pragma unroll
        for (int j = 0; j < IPTN; j++) sip[j] = srow[TXTN + j];
        const int gr = qi >> 6, gc = qi & 63;
        const int region = (gr < 32) ? ((gc < 32) ? 0 : -1)
                                     : ((gc >= 32) ? 1 : -1);
        if (region == 0)      { sip[4] = sip[5] = sip[6] = sip[7] = -1e30f; }
        else if (region == 1) { sip[0] = sip[1] = sip[2] = sip[3] = -1e30f; }

        float l = 0.f;
        for (int j = 0; j < TXTN; j++) {
            float e = __expf(srow[j] - mx);
            l += e;
            srow[j] = e;
        }
        float m2 = -1e30f;
#pragma unroll
        for (int j = 0; j < IPTN; j++) m2 = fmaxf(m2, sip[j]);
        float p2[IPTN], sum2 = 0.f;
#pragma unroll
        for (int j = 0; j < IPTN; j++) { p2[j] = __expf(sip[j] - m2); sum2 += p2[j]; }

        const float wv  = wbuf[b*QLEN + qi];
        const float wmn = mm[2*b], wmx = mm[2*b + 1];
        float aw = (wv - wmn) / (wmx - wmn);
        aw = (aw < 0.3f) ? 0.f : aw;
        aw *= 0.5f;
        if (region >= 0) aw = aw * 2.f + 1.f;
        const float coeff = aw / sum2;
        const float invl = 1.f / l;

        __half* prow = (__half*)srow;   // in-place: P[j] bytes precede S[j] bytes
        for (int j = 0; j < TXTN; j++) {
            float e = srow[j];          // read S[j] before overwriting its low bytes
            prow[j] = __float2half_rn(e * invl);
        }
#pragma unroll
        for (int j = 0; j < IPTN; j++)
            prow[TXTN + j] = __float2half_rn(p2[j] * coeff);
#pragma unroll
        for (int j = 85; j < 96; j++) prow[j] = __float2half_rn(0.f);
    }
    __syncwarp();

    // ---- PV phase: out[32, 64] = P_warp @ V' ----
    {
        uint32_t A[2][6][4];
#pragma unroll
        for (int im = 0; im < 2; im++)
#pragma unroll
            for (int kb = 0; kb < 6; kb++) {
                const __half* pb = (const __half*)(sS + (size_t)(rows0 + 16*im + g)*AT_SS)
                                   + 16*kb + 2*t;
                A[im][kb][0] = *(const uint32_t*)(pb);
                A[im][kb][1] = *(const uint32_t*)(pb + 8*AT_SS*2);
                A[im][kb][2] = *(const uint32_t*)(pb + 8);
                A[im][kb][3] = *(const uint32_t*)(pb + 8*AT_SS*2 + 8);
            }
        float c[2][8][4];
#pragma unroll
        for (int im = 0; im < 2; im++)
#pragma unroll
            for (int jn = 0; jn < 8; jn++)
#pragma unroll
                for (int r = 0; r < 4; r++) c[im][jn][r] = 0.f;
#pragma unroll
        for (int jn = 0; jn < 8; jn++) {
#pragma unroll
            for (int kb = 0; kb < 6; kb++) {
                const __half* vb = sVt + (8*jn + g)*AT_VS + 16*kb + 2*t;
                uint32_t B[2] = { *(const uint32_t*)(vb), *(const uint32_t*)(vb + 8) };
#pragma unroll
                for (int im = 0; im < 2; im++)
                    mma_fp16(c[im][jn], A[im][kb], B);
            }
        }
#pragma unroll
        for (int im = 0; im < 2; im++) {
#pragma unroll
            for (int jn = 0; jn < 8; jn++) {
                int row = q0 + rows0 + 16*im + g;
                int col = h*HDIM + 8*jn + 2*t;
                __half* op  = hid + ((size_t)b*QLEN + row)*HIDD + col;
                __half* op8 = hid + ((size_t)b*QLEN + row + 8)*HIDD + col;
                *(uint32_t*)op  = h2u(__floats2half2_rn(c[im][jn][0], c[im][jn][1]));
                *(uint32_t*)op8 = h2u(__floats2half2_rn(c[im][jn][2], c[im][jn][3]));
            }
        }
    }
}

// ---------------- host launcher ----------------
extern "C" void kernel_launch(void* const* d_in, const int* in_sizes, int n_in,
                              void* d_out, int out_size)
{
    const float* hs     = (const float*)d_in[0];
    const float* enc    = (const float*)d_in[1];
    const float* Wq     = (const float*)d_in[2];
    const float* Wk     = (const float*)d_in[3];
    const float* Wv     = (const float*)d_in[4];
    const float* Wo     = (const float*)d_in[5];
    const float* bo     = (const float*)d_in[6];
    const float* q_down = (const float*)d_in[7];
    const float* q_up   = (const float*)d_in[8];
    const float* k_down = (const float*)d_in[9];
    const float* k_up   = (const float*)d_in[10];
    const float* v_down = (const float*)d_in[11];
    const float* v_up   = (const float*)d_in[12];
    const float* o_down = (const float*)d_in[13];
    const float* o_up   = (const float*)d_in[14];
    const float* Wk_ip  = (const float*)d_in[15];
    const float* Wv_ip  = (const float*)d_in[16];
    float* out = (float*)d_out;

    float *pWq, *pWkR, *pWvR, *pkk, *pvv, *pipk, *pipv;
    float *pehs, *pip, *pipsum, *pipkS, *pwqs, *pw, *pmm;
    __half *pWqT, *pWoT, *phsH, *pqH, *phidH;
    cudaGetSymbolAddress((void**)&pWq,   g_Wq);
    cudaGetSymbolAddress((void**)&pWqT,  g_WqT);
    cudaGetSymbolAddress((void**)&pWoT,  g_WoT);
    cudaGetSymbolAddress((void**)&pWkR,  g_WkR);
    cudaGetSymbolAddress((void**)&pWvR,  g_WvR);
    cudaGetSymbolAddress((void**)&phsH,  g_hsH);
    cudaGetSymbolAddress((void**)&pqH,   g_qH);
    cudaGetSymbolAddress((void**)&phidH, g_hidH);
    cudaGetSymbolAddress((void**)&pkk,   g_kk);
    cudaGetSymbolAddress((void**)&pvv,   g_vv);
    cudaGetSymbolAddress((void**)&pipk,  g_ipk);
    cudaGetSymbolAddress((void**)&pipv,  g_ipv);
    cudaGetSymbolAddress((void**)&pehs,  g_ehs);
    cudaGetSymbolAddress((void**)&pip,   g_ip);
    cudaGetSymbolAddress((void**)&pipsum,g_ipsum);
    cudaGetSymbolAddress((void**)&pipkS, g_ipkS);
    cudaGetSymbolAddress((void**)&pwqs,  g_wqs);
    cudaGetSymbolAddress((void**)&pw,    g_w);
    cudaGetSymbolAddress((void**)&pmm,   g_mm);

    static cudaStream_t s2 = nullptr;
    static cudaEvent_t eO = nullptr, eF = nullptr, eS = nullptr;
    if (s2 == nullptr) {
        cudaStreamCreateWithFlags(&s2, cudaStreamNonBlocking);
        cudaEventCreateWithFlags(&eO, cudaEventDisableTiming);
        cudaEventCreateWithFlags(&eF, cudaEventDisableTiming);
        cudaEventCreateWithFlags(&eS, cudaEventDisableTiming);
        cudaFuncSetAttribute(gemm_fp16<true>,
            cudaFuncAttributeMaxDynamicSharedMemorySize, GH_SMEM);
        cudaFuncSetAttribute(gemm_fp16<false>,
            cudaFuncAttributeMaxDynamicSharedMemorySize, GH_SMEM);
        cudaFuncSetAttribute(attn_kernel,
            cudaFuncAttributeMaxDynamicSharedMemorySize, AT_SMEM);
    }

    // ---- fork point: side stream joins the capture first ----
    cudaEventRecord(eO, 0);
    cudaStreamWaitEvent(s2, eO, 0);

    // ---- main stream: hs->half, fuse Wq, monolithic Q-GEMM (half out) ----
    hs2h_kernel<<<NB*QLEN*HIDD/1024, 256>>>(hs, phsH);
    fuse_t_kernel<<<dim3(32, 32), 256>>>(Wq, q_down, q_up, pWqT, pWq);
    cudaEventRecord(eF, 0);
    gemm_fp16<true><<<dim3(HIDD/128, NB*QLEN/128), 256, GH_SMEM>>>(
        phsH, pWqT, pqH, nullptr, HIDD, HIDD);

    // ---- s2: Wo fuse+transpose, pack, enc/ip GEMMs, exact gate ----
    fuse_t_kernel<<<dim3(32, 32), 256, 0, s2>>>(Wo, o_down, o_up, pWoT, nullptr);
    pack_enc_kernel<<<((NB*TXTN + NB*IPTN)*CDIM + 255)/256, 256, 0, s2>>>(enc, pehs, pip);
    fuse_kv_kernel<<<(2*CDIM*HIDD + 255)/256, 256, 0, s2>>>(
        Wk, k_down, k_up, Wv, v_down, v_up, pWkR, pWvR);
    gemm_encip<<<dim3(HIDD/128, 4, 2), 128, 0, s2>>>(
        pehs, pip, pWkR, pWvR, Wk_ip, Wv_ip, pkk, pvv, pipk, pipv);
    ipsum_kernel<<<(NB*CDIM + 255)/256, 256, 0, s2>>>(pip, pipsum);
    colvec_kernel<<<dim3(HIDD/256, NB), 256, 0, s2>>>(pipsum, Wk_ip, pipkS);
    cudaStreamWaitEvent(s2, eF, 0);          // g_Wq (fp32) ready
    wqs_matvec_kernel<<<dim3(HIDD/8, NB), 256, 0, s2>>>(pWq, pipkS, pwqs);
    wsum_kernel<<<NB*QLEN/8, 256, 0, s2>>>(hs, pwqs, pw);
    minmax_kernel<<<NB, 256, 0, s2>>>(pw, pmm);
    cudaEventRecord(eS, s2);

    // ---- join, then tensor-core attention + O-GEMM ----
    cudaStreamWaitEvent(0, eS, 0);
    attn_kernel<<<dim3(QLEN/128, NHEAD, NB), 128, AT_SMEM>>>(
        pqH, pkk, pvv, pipk, pipv, pw, pmm, phidH);
    gemm_fp16<false><<<dim3(HIDD/128, NB*QLEN/128), 256, GH_SMEM>>>(
        phidH, pWoT, out, bo, HIDD, HIDD);
}

// round 17
// speedup vs baseline: 1.1517x; 1.1517x over previous
#include <cuda_runtime.h>
#include <cuda_fp16.h>
#include <cstdint>
#include <cstring>

#define NB    4
#define QLEN  4096
#define HIDD  1024
#define NHEAD 16
#define HDIM  64
#define TXTN  77
#define IPTN  8
#define CDIM  768
#define ENCR  85   // TXT + IPT

// ---------------- scratch (no allocation allowed) ----------------
__device__ float  g_Wq  [HIDD*HIDD];   // fp32-exact (gate path)
__device__ __half g_WqT [HIDD*HIDD];   // fp16, TRANSPOSED [N,K]
__device__ __half g_WoT [HIDD*HIDD];   // fp16, TRANSPOSED [N,K]
__device__ float  g_WkR [CDIM*HIDD];
__device__ float  g_WvR [CDIM*HIDD];
__device__ __half g_hsH [NB*QLEN*HIDD];  // hs converted to half
__device__ __half g_qH  [NB*QLEN*HIDD];  // Q projection, half
__device__ __half g_hidH[NB*QLEN*HIDD];  // attention output, half
__device__ float  g_kk  [NB*TXTN*HIDD];
__device__ float  g_vv  [NB*TXTN*HIDD];
__device__ float  g_ipk [NB*IPTN*HIDD];
__device__ float  g_ipv [NB*IPTN*HIDD];
__device__ float  g_ehs [NB*TXTN*CDIM];   // pre-rounded to tf32
__device__ float  g_ip  [NB*IPTN*CDIM];   // exact (gate path reads it)
__device__ float  g_ipsum[NB*CDIM];
__device__ float  g_ipkS[NB*HIDD];
__device__ float  g_wqs [NB*HIDD];
__device__ float  g_w   [NB*QLEN];
__device__ float  g_mm  [2*NB];

typedef unsigned long long u64;

__device__ __forceinline__ uint32_t h2u(__half2 h) {
    uint32_t u;
    memcpy(&u, &h, 4);
    return u;
}
__device__ __forceinline__ __half2 u2h(uint32_t u) {
    __half2 h;
    memcpy(&h, &u, 4);
    return h;
}

__device__ __forceinline__ uint32_t f2tf(float x) {
    uint32_t r;
    asm("cvt.rna.tf32.f32 %0, %1;" : "=r"(r) : "f"(x));
    return r;
}
__device__ __forceinline__ float roundtf(float x) {
    return __uint_as_float(f2tf(x));
}
// ---- packed fp32 (FFMA2) helpers ----
__device__ __forceinline__ void fma2(u64& d, u64 a, u64 b) {
    asm("fma.rn.f32x2 %0, %1, %2, %0;" : "+l"(d) : "l"(a), "l"(b));
}
__device__ __forceinline__ void mul2(u64& d, u64 c) {
    asm("mul.rn.f32x2 %0, %0, %1;" : "+l"(d) : "l"(c));
}
__device__ __forceinline__ u64 pack2(float x) {
    u64 r; asm("mov.b64 %0, {%1, %1};" : "=l"(r) : "f"(x)); return r;
}
__device__ __forceinline__ u64 pack2f(float lo, float hi) {
    u64 r; asm("mov.b64 %0, {%1, %2};" : "=l"(r) : "f"(lo), "f"(hi)); return r;
}
__device__ __forceinline__ void unpack2(float& lo, float& hi, u64 v) {
    asm("mov.b64 {%0, %1}, %2;" : "=f"(lo), "=f"(hi) : "l"(v));
}

__device__ __forceinline__ void cp16g(uint32_t s, const void* g) {
    asm volatile("cp.async.ca.shared.global [%0], [%1], 16;" :: "r"(s), "l"(g));
}
__device__ __forceinline__ void cp_commit() {
    asm volatile("cp.async.commit_group;");
}
template<int N_> __device__ __forceinline__ void cp_wait() {
    asm volatile("cp.async.wait_group %0;" :: "n"(N_));
}

// ================= FP16 tensor-core GEMM: C[M,N] = A[M,K] @ Bt[N,K]^T ========
// mma.sync.m16n8k16 f16. CTA 128x128, BK=64 halves, 256 threads (8 warps 32x64).
#define HPAD 72
#define GH_STAGE (128*HPAD*2)
#define GH_SMEM  (4*GH_STAGE)

__device__ __forceinline__ void mma_fp16(float* c, const uint32_t* a, const uint32_t* b) {
    asm volatile("mma.sync.aligned.m16n8k16.row.col.f32.f16.f16.f32 "
        "{%0,%1,%2,%3}, {%4,%5,%6,%7}, {%8,%9}, {%0,%1,%2,%3};"
        : "+f"(c[0]), "+f"(c[1]), "+f"(c[2]), "+f"(c[3])
        : "r"(a[0]), "r"(a[1]), "r"(a[2]), "r"(a[3]), "r"(b[0]), "r"(b[1]));
}

template<bool HOUT>
__global__ __launch_bounds__(256) void gemm_fp16(
    const __half* __restrict__ A, const __half* __restrict__ Bt,
    void* __restrict__ Cv, const float* __restrict__ bias, int K, int N)
{
    extern __shared__ __align__(16) char sm[];
    const uint32_t sA = (uint32_t)__cvta_generic_to_shared(sm);
    const uint32_t sB = sA + 2*GH_STAGE;

    const int tid  = threadIdx.x;
    const int lane = tid & 31;
    const int warp = tid >> 5;
    const int wm = (warp >> 1) * 32;
    const int wn = (warp & 1) * 64;
    const int row0 = blockIdx.y * 128;
    const int n0   = blockIdx.x * 128;

    const __half* Ab = A  + (size_t)row0 * K;
    const __half* Bb = Bt + (size_t)n0 * K;

    float acc[2][8][4];
#pragma unroll
    for (int i = 0; i < 2; i++)
#pragma unroll
        for (int j = 0; j < 8; j++)
#pragma unroll
            for (int r = 0; r < 4; r++) acc[i][j][r] = 0.f;

    auto load_stage = [&](int s, int buf) {
        const uint32_t ab = sA + (uint32_t)buf * GH_STAGE;
        const uint32_t bb = sB + (uint32_t)buf * GH_STAGE;
        const int k0 = s * 64;
#pragma unroll
        for (int i = 0; i < 4; i++) {
            int c = tid + 256 * i;
            int r = c >> 3, cc = c & 7;
            cp16g(ab + (uint32_t)(r * (HPAD*2) + cc * 16),
                  Ab + (size_t)r * K + k0 + cc * 8);
            cp16g(bb + (uint32_t)(r * (HPAD*2) + cc * 16),
                  Bb + (size_t)r * K + k0 + cc * 8);
        }
    };

    const int nstage = K / 64;
    load_stage(0, 0);
    cp_commit();

    for (int s = 0; s < nstage; s++) {
        const int buf = s & 1;
        if (s + 1 < nstage) {
            load_stage(s + 1, buf ^ 1);
            cp_commit();
            cp_wait<1>();
        } else {
            cp_wait<0>();
        }
        __syncthreads();

        const uint32_t ab = sA + (uint32_t)buf * GH_STAGE;
        const uint32_t bb = sB + (uint32_t)buf * GH_STAGE;
        const int g = lane >> 2, t = lane & 3;

#pragma unroll
        for (int ks = 0; ks < 64; ks += 16) {
            uint32_t af[2][4];
#pragma unroll
            for (int im = 0; im < 2; im++) {
                uint32_t base = ab + (uint32_t)((wm + im*16 + g) * (HPAD*2) + (ks + 2*t) * 2);
                asm volatile("ld.shared.b32 %0, [%1];" : "=r"(af[im][0]) : "r"(base));
                asm volatile("ld.shared.b32 %0, [%1];" : "=r"(af[im][1]) : "r"(base + 8*(HPAD*2)));
                asm volatile("ld.shared.b32 %0, [%1];" : "=r"(af[im][2]) : "r"(base + 16));
                asm volatile("ld.shared.b32 %0, [%1];" : "=r"(af[im][3]) : "r"(base + 8*(HPAD*2) + 16));
            }
            uint32_t bf[8][2];
#pragma unroll
            for (int jn = 0; jn < 8; jn++) {
                uint32_t base = bb + (uint32_t)((wn + jn*8 + g) * (HPAD*2) + (ks + 2*t) * 2);
                asm volatile("ld.shared.b32 %0, [%1];" : "=r"(bf[jn][0]) : "r"(base));
                asm volatile("ld.shared.b32 %0, [%1];" : "=r"(bf[jn][1]) : "r"(base + 16));
            }
#pragma unroll
            for (int im = 0; im < 2; im++)
#pragma unroll
                for (int jn = 0; jn < 8; jn++)
                    mma_fp16(acc[im][jn], af[im], bf[jn]);
        }
        __syncthreads();
    }

#pragma unroll
    for (int im = 0; im < 2; im++) {
#pragma unroll
        for (int jn = 0; jn < 8; jn++) {
            int r = row0 + wm + im*16 + (lane >> 2);
            int c = n0 + wn + jn*8 + 2*(lane & 3);
            float2 v0 = make_float2(acc[im][jn][0], acc[im][jn][1]);
            float2 v1 = make_float2(acc[im][jn][2], acc[im][jn][3]);
            if (HOUT) {
                __half* C = (__half*)Cv;
                *(uint32_t*)(C + (size_t)r*N + c)       = h2u(__floats2half2_rn(v0.x, v0.y));
                *(uint32_t*)(C + (size_t)(r + 8)*N + c) = h2u(__floats2half2_rn(v1.x, v1.y));
            } else {
                float* C = (float*)Cv;
                if (bias) {
                    float2 bv = *(const float2*)(bias + c);
                    v0.x += bv.x; v0.y += bv.y;
                    v1.x += bv.x; v1.y += bv.y;
                }
                *(float2*)(C + (size_t)r*N + c)       = v0;
                *(float2*)(C + (size_t)(r + 8)*N + c) = v1;
            }
        }
    }
}

// ---------------- hs -> half (one-time convert) ----------------
__global__ void hs2h_kernel(const float* __restrict__ hs, __half* __restrict__ out)
{
    int i = (blockIdx.x * 256 + threadIdx.x) * 4;
    float4 v = *(const float4*)(hs + i);
    __half2 h0 = __floats2half2_rn(v.x, v.y);
    __half2 h1 = __floats2half2_rn(v.z, v.w);
    uint2 w = make_uint2(h2u(h0), h2u(h1));
    *(uint2*)(out + i) = w;
}

// ---------------- fuse + transpose (Wq / Wo): out half [N,K] ----------------
__global__ __launch_bounds__(256) void fuse_t_kernel(
    const float* __restrict__ W, const float* __restrict__ dn,
    const float* __restrict__ up, __half* __restrict__ outT,
    float* __restrict__ outF)
{
    __shared__ float t[32][33];
    const int bx = blockIdx.x, by = blockIdx.y;
    const int tx = threadIdx.x & 31, ty = threadIdx.x >> 5;
#pragma unroll
    for (int i = 0; i < 4; i++) {
        int rr = by * 32 + ty + 8 * i;
        int cc = bx * 32 + tx;
        float acc = W[rr * HIDD + cc];
#pragma unroll
        for (int j = 0; j < 4; j++)
            acc = fmaf(dn[rr * 4 + j], up[j * HIDD + cc], acc);
        if (outF) outF[rr * HIDD + cc] = acc;
        t[ty + 8 * i][tx] = acc;
    }
    __syncthreads();
#pragma unroll
    for (int i = 0; i < 4; i++) {
        int rr = by * 32 + tx;
        int cc = bx * 32 + ty + 8 * i;
        outT[(size_t)cc * HIDD + rr] = __float2half_rn(t[tx][ty + 8 * i]);
    }
}

// ---------------- fold LoRA into Wk/Wv (untransposed, tf32-rounded) ----------
__global__ void fuse_kv_kernel(
    const float* __restrict__ Wk, const float* __restrict__ kd, const float* __restrict__ ku,
    const float* __restrict__ Wv, const float* __restrict__ vd, const float* __restrict__ vu,
    float* __restrict__ oWkR, float* __restrict__ oWvR)
{
    const int NK = CDIM*HIDD;
    int idx = blockIdx.x * 256 + threadIdx.x;
    const float *W, *dn, *up;
    float* oR;
    int li;
    if (idx < NK)        { W=Wk; dn=kd; up=ku; oR=oWkR; li=idx; }
    else if (idx < 2*NK) { W=Wv; dn=vd; up=vu; oR=oWvR; li=idx-NK; }
    else return;
    int r = li >> 10, c = li & 1023;
    float acc = W[li];
#pragma unroll
    for (int j = 0; j < 4; j++)
        acc = fmaf(dn[r*4 + j], up[j*HIDD + c], acc);
    oR[li] = roundtf(acc);
}

// ---------------- pack encoder slices contiguous ----------------
__global__ void pack_enc_kernel(const float* __restrict__ enc,
                                float* __restrict__ ehs,
                                float* __restrict__ ipb)
{
    int idx = blockIdx.x * 256 + threadIdx.x;
    const int n1 = NB*TXTN*CDIM;
    const int n2 = NB*IPTN*CDIM;
    if (idx < n1) {
        int b = idx / (TXTN*CDIM);
        int rem = idx - b*(TXTN*CDIM);
        int t = rem / CDIM, c = rem - t*CDIM;
        ehs[idx] = roundtf(enc[((size_t)b*ENCR + t)*CDIM + c]);
    } else if (idx < n1 + n2) {
        int k = idx - n1;
        int b = k / (IPTN*CDIM);
        int rem = k - b*(IPTN*CDIM);
        int t = rem / CDIM, c = rem - t*CDIM;
        ipb[k] = enc[((size_t)b*ENCR + TXTN + t)*CDIM + c];
    }
}

// ================= mma.sync TF32 GEMM body (small enc/ip projections) =======
#define APAD 20
#define BPAD 136

__device__ __forceinline__ void mma_tf32(float* c, const uint32_t* a, const uint32_t* b) {
    asm volatile("mma.sync.aligned.m16n8k8.row.col.f32.tf32.tf32.f32 "
        "{%0,%1,%2,%3}, {%4,%5,%6,%7}, {%8,%9}, {%0,%1,%2,%3};"
        : "+f"(c[0]), "+f"(c[1]), "+f"(c[2]), "+f"(c[3])
        : "r"(a[0]), "r"(a[1]), "r"(a[2]), "r"(a[3]), "r"(b[0]), "r"(b[1]));
}
__device__ __forceinline__ uint32_t ldfragc(const float* p) {
    return f2tf(*p);
}

__device__ __forceinline__ void gemm_body_tf32(
    const float* __restrict__ A, const float* __restrict__ B,
    float* __restrict__ C, int M, int N, int K, int bx, int by)
{
    __shared__ float As[2][128*APAD];
    __shared__ float Bs[2][16*BPAD];

    const int tid  = threadIdx.x;
    const int lane = tid & 31;
    const int warp = tid >> 5;
    const int wm = (warp >> 1) * 64;
    const int wn = (warp & 1) * 64;

    const float* Bg = B + bx * 128;

    const int a_colv = tid & 3;
    const int a_rowb = tid >> 2;
    const int b_colv = tid & 31;
    const int b_rowb = tid >> 5;

    const uint32_t as0 = (uint32_t)__cvta_generic_to_shared(&As[0][0]);
    const uint32_t bs0 = (uint32_t)__cvta_generic_to_shared(&Bs[0][0]);

    float acc[4][8][4];
#pragma unroll
    for (int i = 0; i < 4; i++)
#pragma unroll
        for (int j = 0; j < 8; j++)
#pragma unroll
            for (int r = 0; r < 4; r++) acc[i][j][r] = 0.f;

    auto load_stage = [&](int k0, int buf) {
        uint32_t asb = as0 + (uint32_t)buf * (128*APAD*4);
        uint32_t bsb = bs0 + (uint32_t)buf * (16*BPAD*4);
#pragma unroll
        for (int i = 0; i < 4; i++) {
            int row = a_rowb + i*32;
            int rg = by*128 + row; if (rg > M-1) rg = M-1;
            cp16g(asb + (uint32_t)(row*APAD + a_colv*4)*4,
                 A + (size_t)rg*K + k0 + a_colv*4);
        }
#pragma unroll
        for (int i = 0; i < 4; i++) {
            int row = b_rowb + i*4;
            cp16g(bsb + (uint32_t)(row*BPAD + b_colv*4)*4,
                 Bg + (size_t)(k0 + row)*N + b_colv*4);
        }
    };

    const int nstage = K / 16;
    load_stage(0, 0);
    cp_commit();

    int buf = 0;
    for (int s = 0; s < nstage; s++) {
        if (s + 1 < nstage) {
            load_stage((s + 1)*16, buf ^ 1);
            cp_commit();
            cp_wait<1>();
        } else {
            cp_wait<0>();
        }
        __syncthreads();

        const float* as = As[buf];
        const float* bs = Bs[buf];
#pragma unroll
        for (int ks = 0; ks < 16; ks += 8) {
            uint32_t af[4][4];
#pragma unroll
            for (int im = 0; im < 4; im++) {
                const float* ap = as + (wm + im*16 + (lane >> 2))*APAD + ks + (lane & 3);
                af[im][0] = ldfragc(ap);
                af[im][1] = ldfragc(ap + 8*APAD);
                af[im][2] = ldfragc(ap + 4);
                af[im][3] = ldfragc(ap + 8*APAD + 4);
            }
            uint32_t bf[8][2];
#pragma unroll
            for (int jn = 0; jn < 8; jn++) {
                const float* bp = bs + (ks + (lane & 3))*BPAD + wn + jn*8 + (lane >> 2);
                bf[jn][0] = ldfragc(bp);
                bf[jn][1] = ldfragc(bp + 4*BPAD);
            }
#pragma unroll
            for (int im = 0; im < 4; im++)
#pragma unroll
                for (int jn = 0; jn < 8; jn++)
                    mma_tf32(acc[im][jn], af[im], bf[jn]);
        }
        __syncthreads();
        buf ^= 1;
    }

#pragma unroll
    for (int im = 0; im < 4; im++) {
#pragma unroll
        for (int jn = 0; jn < 8; jn++) {
            int r = by*128 + wm + im*16 + (lane >> 2);
            int c = bx*128 + wn + jn*8 + 2*(lane & 3);
            float2 v0 = make_float2(acc[im][jn][0], acc[im][jn][1]);
            float2 v1 = make_float2(acc[im][jn][2], acc[im][jn][3]);
            if (r < M)     *(float2*)(C + (size_t)r*N + c)       = v0;
            if (r + 8 < M) *(float2*)(C + (size_t)(r + 8)*N + c) = v1;
        }
    }
}

__global__ __launch_bounds__(128, 2) void gemm_encip(
    const float* __restrict__ ehs, const float* __restrict__ ipb,
    const float* __restrict__ WkR, const float* __restrict__ WvR,
    const float* __restrict__ Wk_ip, const float* __restrict__ Wv_ip,
    float* __restrict__ kk, float* __restrict__ vv,
    float* __restrict__ ipk, float* __restrict__ ipv)
{
    const int y = blockIdx.y, z = blockIdx.z;
    const float *A, *B; float* C; int M, by;
    if (y < 3) { A = ehs; M = NB*TXTN; by = y; B = z ? WvR  : WkR;   C = z ? vv  : kk;  }
    else       { A = ipb; M = NB*IPTN; by = 0; B = z ? Wv_ip : Wk_ip; C = z ? ipv : ipk; }
    gemm_body_tf32(A, B, C, M, HIDD, CDIM, blockIdx.x, by);
}

// ---------------- exact fp32 gate path ----------------
__global__ void ipsum_kernel(const float* __restrict__ ip, float* __restrict__ out)
{
    int idx = blockIdx.x * 256 + threadIdx.x;
    if (idx >= NB * CDIM) return;
    int b = idx / CDIM, c = idx - b*CDIM;
    float s = 0.f;
#pragma unroll
    for (int t = 0; t < IPTN; t++)
        s += ip[((size_t)b*IPTN + t)*CDIM + c];
    out[idx] = s;
}

__global__ __launch_bounds__(256) void colvec_kernel(
    const float* __restrict__ s, const float* __restrict__ W,
    float* __restrict__ out)
{
    __shared__ float ss[CDIM];
    const int b = blockIdx.y;
    const int j = blockIdx.x * 256 + threadIdx.x;
    for (int i = threadIdx.x; i < CDIM; i += 256) ss[i] = s[b*CDIM + i];
    __syncthreads();
    float acc = 0.f;
#pragma unroll 8
    for (int i = 0; i < CDIM; i++)
        acc = fmaf(ss[i], W[(size_t)i*HIDD + j], acc);
    out[b*HIDD + j] = acc;
}

__global__ __launch_bounds__(256) void wqs_matvec_kernel(
    const float* __restrict__ W, const float* __restrict__ s,
    float* __restrict__ v)
{
    __shared__ float sv[HIDD];
    const int b = blockIdx.y;
    for (int i = threadIdx.x; i < HIDD; i += 256) sv[i] = s[b*HIDD + i];
    __syncthreads();
    const int warp = threadIdx.x >> 5, lane = threadIdx.x & 31;
    const int row = blockIdx.x * 8 + warp;
    const float* wr = W + (size_t)row * HIDD;
    float acc = 0.f;
#pragma unroll
    for (int i = 0; i < 32; i++)
        acc = fmaf(wr[lane + 32*i], sv[lane + 32*i], acc);
#pragma unroll
    for (int off = 16; off > 0; off >>= 1)
        acc += __shfl_xor_sync(0xffffffffu, acc, off);
    if (lane == 0) v[b*HIDD + row] = acc;
}

__global__ __launch_bounds__(256) void wsum_kernel(const float* __restrict__ hs,
                                                   const float* __restrict__ vb,
                                                   float* __restrict__ w)
{
    __shared__ float sk[HIDD];
    const int row0 = blockIdx.x * 8;
    const int b = row0 / QLEN;
    for (int i = threadIdx.x; i < HIDD; i += 256) sk[i] = vb[b*HIDD + i];
    __syncthreads();
    const int warp = threadIdx.x >> 5, lane = threadIdx.x & 31;
    const int row = row0 + warp;
    const float* qr = hs + (size_t)row * HIDD;
    float s = 0.f;
#pragma unroll
    for (int i = 0; i < 32; i++)
        s = fmaf(qr[lane + 32*i], sk[lane + 32*i], s);
#pragma unroll
    for (int off = 16; off > 0; off >>= 1)
        s += __shfl_xor_sync(0xffffffffu, s, off);
    if (lane == 0) w[row] = 0.125f * s;
}

__global__ void minmax_kernel(const float* __restrict__ w, float* __restrict__ mm)
{
    __shared__ float smn[256], smx[256];
    const int b = blockIdx.x, tid = threadIdx.x;
    float mn = 1e30f, mx = -1e30f;
    for (int i = tid; i < QLEN; i += 256) {
        float v = w[b*QLEN + i];
        mn = fminf(mn, v); mx = fmaxf(mx, v);
    }
    smn[tid] = mn; smx[tid] = mx;
    __syncthreads();
    for (int s = 128; s > 0; s >>= 1) {
        if (tid < s) {
            smn[tid] = fminf(smn[tid], smn[tid + s]);
            smx[tid] = fmaxf(smx[tid], smx[tid + s]);
        }
        __syncthreads();
    }
    if (tid == 0) { mm[2*b] = smn[0]; mm[2*b + 1] = smx[0]; }
}

// ---------------- fused attention (packed fp32 / FFMA2; q half in, half out) -
__global__ __launch_bounds__(128) void attn_kernel(
    const __half* __restrict__ qb,
    const float* __restrict__ kk,
    const float* __restrict__ vv,
    const float* __restrict__ ipk,
    const float* __restrict__ ipv,
    const float* __restrict__ wbuf,
    const float* __restrict__ mm,
    __half* __restrict__ hid)
{
    __shared__ __align__(16) float smem[TXTN*HDIM*2 + IPTN*HDIM*2];
    float* sK  = smem;
    float* sV  = smem + TXTN*HDIM;
    float* sIK = smem + 2*TXTN*HDIM;
    float* sIV = sIK + IPTN*HDIM;

    const int tid = threadIdx.x;
    const int b = blockIdx.z, h = blockIdx.y, q0 = blockIdx.x * 128;

    const size_t kvbase = ((size_t)b*TXTN)*HIDD + h*HDIM;
    for (int i = tid; i < TXTN*HDIM; i += 128) {
        int t = i >> 6, d = i & 63;
        sK[i] = kk[kvbase + (size_t)t*HIDD + d];
        sV[i] = vv[kvbase + (size_t)t*HIDD + d];
    }
    const size_t ipbase = ((size_t)b*IPTN)*HIDD + h*HDIM;
    for (int i = tid; i < IPTN*HDIM; i += 128) {
        int t = i >> 6, d = i & 63;
        sIK[i] = ipk[ipbase + (size_t)t*HIDD + d];
        sIV[i] = ipv[ipbase + (size_t)t*HIDD + d];
    }
    __syncthreads();

    const int qi = q0 + tid;

    u64 q2[32];
    {
        const uint4* qp = (const uint4*)(qb + ((size_t)b*QLEN + qi)*HIDD + h*HDIM);
        const u64 eighth = pack2(0.125f);
#pragma unroll
        for (int i = 0; i < 8; i++) {
            uint4 v = qp[i];
            uint32_t ws[4] = {v.x, v.y, v.z, v.w};
#pragma unroll
            for (int j = 0; j < 4; j++) {
                float2 f = __half22float2(u2h(ws[j]));
                q2[i*4 + j] = pack2f(f.x, f.y);
            }
        }
#pragma unroll
        for (int i = 0; i < 32; i++) mul2(q2[i], eighth);
    }

    float m = -1e30f, l = 0.f;
    u64 o2[32];
#pragma unroll
    for (int i = 0; i < 32; i++) o2[i] = 0ULL;

    for (int t = 0; t < TXTN; t++) {
        const u64* kp = (const u64*)(sK + t*HDIM);
        u64 a = 0ULL;
#pragma unroll
        for (int i = 0; i < 32; i++) fma2(a, q2[i], kp[i]);
        float lo, hi; unpack2(lo, hi, a);
        float s = lo + hi;
        if (s > m) {
            float c = __expf(m - s);
            l *= c;
            u64 cc = pack2(c);
#pragma unroll
            for (int i = 0; i < 32; i++) mul2(o2[i], cc);
            m = s;
        }
        float p = __expf(s - m);
        l += p;
        u64 pp = pack2(p);
        const u64* vp = (const u64*)(sV + t*HDIM);
#pragma unroll
        for (int i = 0; i < 32; i++) fma2(o2[i], pp, vp[i]);
    }
    const float inv_l = 1.f / l;

    float sip[IPTN];
#pragma unroll
    for (int t = 0; t < IPTN; t++) {
        const u64* kp = (const u64*)(sIK + t*HDIM);
        u64 a = 0ULL;
#pragma unroll
        for (int i = 0; i < 32; i++) fma2(a, q2[i], kp[i]);
        float lo, hi; unpack2(lo, hi, a);
        sip[t] = lo + hi;
    }
    const int gr = qi >> 6, gc = qi & 63;
    const int region = (gr < 32) ? ((gc < 32) ? 0 : -1)
                                 : ((gc >= 32) ? 1 : -1);
    if (region == 0) { sip[4] = sip[5] = sip[6] = sip[7] = -1e30f; }
    else if (region == 1) { sip[0] = sip[1] = sip[2] = sip[3] = -1e30f; }

    float m2 = -1e30f;
#pragma unroll
    for (int t = 0; t < IPTN; t++) m2 = fmaxf(m2, sip[t]);
    float p2[IPTN], sum2 = 0.f;
#pragma unroll
    for (int t = 0; t < IPTN; t++) { p2[t] = __expf(sip[t] - m2); sum2 += p2[t]; }

    const float wv  = wbuf[b*QLEN + qi];
    const float wmn = mm[2*b], wmx = mm[2*b + 1];
    float aw = (wv - wmn) / (wmx - wmn);
    aw = (aw < 0.3f) ? 0.f : aw;
    aw *= 0.5f;
    if (region >= 0) aw = aw * 2.f + 1.f;
    const float coeff = aw / sum2;

    u64 pp2[IPTN];
#pragma unroll
    for (int t = 0; t < IPTN; t++) pp2[t] = pack2(p2[t]);
    const u64 invl2 = pack2(inv_l);
    const u64 co2   = pack2(coeff);

    __syncthreads();
    float* so = smem;
    const u64* iv = (const u64*)sIV;
#pragma unroll
    for (int i = 0; i < 32; i++) {
        u64 ipa = 0ULL;
#pragma unroll
        for (int t = 0; t < IPTN; t++) fma2(ipa, pp2[t], iv[t*32 + i]);
        mul2(o2[i], invl2);
        fma2(o2[i], co2, ipa);
        float lo, hi; unpack2(lo, hi, o2[i]);
        so[tid*68 + 2*i]     = lo;
        so[tid*68 + 2*i + 1] = hi;
    }
    __syncthreads();

    __half* outp = hid + ((size_t)b*QLEN + q0)*HIDD + h*HDIM;
    for (int i4 = tid; i4 < 128*16; i4 += 128) {
        int r = i4 >> 4, c = i4 & 15;
        float4 v = *(const float4*)(so + r*68 + c*4);
        __half2 h0 = __floats2half2_rn(v.x, v.y);
        __half2 h1 = __floats2half2_rn(v.z, v.w);
        uint2 w = make_uint2(h2u(h0), h2u(h1));
        *(uint2*)(outp + (size_t)r*HIDD + c*4) = w;
    }
}

// ---------------- host launcher ----------------
extern "C" void kernel_launch(void* const* d_in, const int* in_sizes, int n_in,
                              void* d_out, int out_size)
{
    const float* hs     = (const float*)d_in[0];
    const float* enc    = (const float*)d_in[1];
    const float* Wq     = (const float*)d_in[2];
    const float* Wk     = (const float*)d_in[3];
    const float* Wv     = (const float*)d_in[4];
    const float* Wo     = (const float*)d_in[5];
    const float* bo     = (const float*)d_in[6];
    const float* q_down = (const float*)d_in[7];
    const float* q_up   = (const float*)d_in[8];
    const float* k_down = (const float*)d_in[9];
    const float* k_up   = (const float*)d_in[10];
    const float* v_down = (const float*)d_in[11];
    const float* v_up   = (const float*)d_in[12];
    const float* o_down = (const float*)d_in[13];
    const float* o_up   = (const float*)d_in[14];
    const float* Wk_ip  = (const float*)d_in[15];
    const float* Wv_ip  = (const float*)d_in[16];
    float* out = (float*)d_out;

    float *pWq, *pWkR, *pWvR, *pkk, *pvv, *pipk, *pipv;
    float *pehs, *pip, *pipsum, *pipkS, *pwqs, *pw, *pmm;
    __half *pWqT, *pWoT, *phsH, *pqH, *phidH;
    cudaGetSymbolAddress((void**)&pWq,   g_Wq);
    cudaGetSymbolAddress((void**)&pWqT,  g_WqT);
    cudaGetSymbolAddress((void**)&pWoT,  g_WoT);
    cudaGetSymbolAddress((void**)&pWkR,  g_WkR);
    cudaGetSymbolAddress((void**)&pWvR,  g_WvR);
    cudaGetSymbolAddress((void**)&phsH,  g_hsH);
    cudaGetSymbolAddress((void**)&pqH,   g_qH);
    cudaGetSymbolAddress((void**)&phidH, g_hidH);
    cudaGetSymbolAddress((void**)&pkk,   g_kk);
    cudaGetSymbolAddress((void**)&pvv,   g_vv);
    cudaGetSymbolAddress((void**)&pipk,  g_ipk);
    cudaGetSymbolAddress((void**)&pipv,  g_ipv);
    cudaGetSymbolAddress((void**)&pehs,  g_ehs);
    cudaGetSymbolAddress((void**)&pip,   g_ip);
    cudaGetSymbolAddress((void**)&pipsum,g_ipsum);
    cudaGetSymbolAddress((void**)&pipkS, g_ipkS);
    cudaGetSymbolAddress((void**)&pwqs,  g_wqs);
    cudaGetSymbolAddress((void**)&pw,    g_w);
    cudaGetSymbolAddress((void**)&pmm,   g_mm);

    static cudaStream_t s2 = nullptr;
    static cudaEvent_t eO = nullptr, eF2 = nullptr, eS = nullptr;
    if (s2 == nullptr) {
        cudaStreamCreateWithFlags(&s2, cudaStreamNonBlocking);
        cudaEventCreateWithFlags(&eO, cudaEventDisableTiming);
        cudaEventCreateWithFlags(&eF2, cudaEventDisableTiming);
        cudaEventCreateWithFlags(&eS, cudaEventDisableTiming);
        cudaFuncSetAttribute(gemm_fp16<true>,
            cudaFuncAttributeMaxDynamicSharedMemorySize, GH_SMEM);
        cudaFuncSetAttribute(gemm_fp16<false>,
            cudaFuncAttributeMaxDynamicSharedMemorySize, GH_SMEM);
    }

    // ---- fork point: side stream joins the capture first ----
    cudaEventRecord(eO, 0);
    cudaStreamWaitEvent(s2, eO, 0);

    // ---- s2 head: fuse Wq (runs concurrently with hs2h on main) ----
    fuse_t_kernel<<<dim3(32, 32), 256, 0, s2>>>(Wq, q_down, q_up, pWqT, pWq);
    cudaEventRecord(eF2, s2);

    // ---- main stream: hs->half, then monolithic Q-GEMM (half out) ----
    hs2h_kernel<<<NB*QLEN*HIDD/1024, 256>>>(hs, phsH);
    cudaStreamWaitEvent(0, eF2, 0);          // WqT ready
    gemm_fp16<true><<<dim3(HIDD/128, NB*QLEN/128), 256, GH_SMEM>>>(
        phsH, pWqT, pqH, nullptr, HIDD, HIDD);

    // ---- s2 tail: Wo fuse+transpose, pack, enc/ip GEMMs, exact gate ----
    fuse_t_kernel<<<dim3(32, 32), 256, 0, s2>>>(Wo, o_down, o_up, pWoT, nullptr);
    pack_enc_kernel<<<((NB*TXTN + NB*IPTN)*CDIM + 255)/256, 256, 0, s2>>>(enc, pehs, pip);
    fuse_kv_kernel<<<(2*CDIM*HIDD + 255)/256, 256, 0, s2>>>(
        Wk, k_down, k_up, Wv, v_down, v_up, pWkR, pWvR);
    gemm_encip<<<dim3(HIDD/128, 4, 2), 128, 0, s2>>>(
        pehs, pip, pWkR, pWvR, Wk_ip, Wv_ip, pkk, pvv, pipk, pipv);
    ipsum_kernel<<<(NB*CDIM + 255)/256, 256, 0, s2>>>(pip, pipsum);
    colvec_kernel<<<dim3(HIDD/256, NB), 256, 0, s2>>>(pipsum, Wk_ip, pipkS);
    wqs_matvec_kernel<<<dim3(HIDD/8, NB), 256, 0, s2>>>(pWq, pipkS, pwqs);   // pWq in-stream
    wsum_kernel<<<NB*QLEN/8, 256, 0, s2>>>(hs, pwqs, pw);
    minmax_kernel<<<NB, 256, 0, s2>>>(pw, pmm);
    cudaEventRecord(eS, s2);

    // ---- join, then attention (half q in, half out) + O-GEMM (fp32 out) ----
    cudaStreamWaitEvent(0, eS, 0);
    attn_kernel<<<dim3(QLEN/128, NHEAD, NB), 128>>>(
        pqH, pkk, pvv, pipk, pipv, pw, pmm, phidH);
    gemm_fp16<false><<<dim3(HIDD/128, NB*QLEN/128), 256, GH_SMEM>>>(
        phidH, pWoT, out, bo, HIDD, HIDD);
}